// round 1
// baseline (speedup 1.0000x reference)
#include <cuda_runtime.h>
#include <cuda_bf16.h>

#define BB 8
#define NN 1024
#define CC 256
#define HH 8
#define HD 32
#define TABLE 10

// Scratch (allocation-free rule: __device__ globals)
__device__ float g_q[BB*HH*NN*HD];
__device__ float g_k[BB*HH*NN*HD];
__device__ float g_v[BB*HH*NN*HD];
__device__ float g_x[BB*NN*CC];

// ---------------------------------------------------------------------------
// Kernel 1: QKV projection. X[8192,256] @ W[256,768] -> scatter q/k/v [B,H,N,hd]
// ---------------------------------------------------------------------------
__global__ void __launch_bounds__(256) qkv_gemm_kernel(
    const float* __restrict__ X, const float* __restrict__ W)
{
    __shared__ float As[16][68];   // As[kk][m]
    __shared__ float Bs[16][68];   // Bs[kk][n]
    const int tid = threadIdx.x;
    const int tx = tid & 15, ty = tid >> 4;
    const int m0 = blockIdx.y * 64, n0 = blockIdx.x * 64;

    float acc[4][4];
    #pragma unroll
    for (int i = 0; i < 4; i++)
        #pragma unroll
        for (int j = 0; j < 4; j++) acc[i][j] = 0.f;

    for (int k0 = 0; k0 < 256; k0 += 16) {
        // Load A tile (64 rows x 16 k), transposed into As[kk][m]
        {
            int r  = tid >> 2;
            int kc = (tid & 3) << 2;
            float4 a = *(const float4*)&X[(m0 + r) * 256 + k0 + kc];
            As[kc+0][r] = a.x; As[kc+1][r] = a.y;
            As[kc+2][r] = a.z; As[kc+3][r] = a.w;
        }
        // Load B tile (16 k x 64 cols)
        {
            int r2 = tid >> 4;
            int c  = (tid & 15) << 2;
            *(float4*)&Bs[r2][c] = *(const float4*)&W[(k0 + r2) * 768 + n0 + c];
        }
        __syncthreads();
        #pragma unroll
        for (int kk = 0; kk < 16; kk++) {
            float4 av = *(float4*)&As[kk][ty << 2];
            float4 bv = *(float4*)&Bs[kk][tx << 2];
            float a4[4] = {av.x, av.y, av.z, av.w};
            float b4[4] = {bv.x, bv.y, bv.z, bv.w};
            #pragma unroll
            for (int i = 0; i < 4; i++)
                #pragma unroll
                for (int j = 0; j < 4; j++) acc[i][j] += a4[i] * b4[j];
        }
        __syncthreads();
    }

    // Scatter: col c = sel*256 + h*32 + d
    #pragma unroll
    for (int i = 0; i < 4; i++) {
        int m = m0 + (ty << 2) + i;
        int b = m >> 10, n = m & 1023;
        #pragma unroll
        for (int j = 0; j < 4; j++) {
            int c   = n0 + (tx << 2) + j;
            int sel = c >> 8;
            int h   = (c & 255) >> 5;
            int d   = c & 31;
            float* dst = (sel == 0) ? g_q : ((sel == 1) ? g_k : g_v);
            dst[(((b * HH) + h) * NN + n) * HD + d] = acc[i][j];
        }
    }
}

// ---------------------------------------------------------------------------
// Kernel 2: fused flash attention with relative-position bias + mask.
// Block = (batch b, 32-row chunk). 8 warps = 8 heads; lane = query row.
// rp tile shared across all heads -> relation_position read exactly once.
// ---------------------------------------------------------------------------
__global__ void __launch_bounds__(256, 2) attn_kernel(
    const int* __restrict__ rp, const int* __restrict__ rel_len,
    const float* __restrict__ bias_table)
{
    extern __shared__ char smem_raw[];
    float* k_s  = (float*)smem_raw;          // [8][32][32]
    float* v_s  = k_s + 8 * 32 * 32;         // [8][32][32]
    int*   rp_s = (int*)(v_s + 8 * 32 * 32); // [32][33] padded
    float* bt_s = (float*)(rp_s + 32 * 33);  // [10][8]

    const int tid   = threadIdx.x;
    const int h     = tid >> 5;   // warp = head
    const int r     = tid & 31;   // lane = row within chunk
    const int b     = blockIdx.x >> 5;
    const int chunk = blockIdx.x & 31;
    const int row   = chunk * 32 + r;

    if (tid < TABLE * HH) bt_s[tid] = bias_table[tid];
    const int mask_len = (int)(__int2float_rn(rel_len[b]) * 0.5f);
    const float scale = 0.17677669529663687f;   // 32^-0.5

    // Load q row (32 floats) into registers
    float q[32];
    {
        const float* qp = &g_q[(((b * HH) + h) * NN + row) * HD];
        #pragma unroll
        for (int i = 0; i < 8; i++) {
            float4 t = *(const float4*)&qp[i * 4];
            q[i*4+0] = t.x; q[i*4+1] = t.y; q[i*4+2] = t.z; q[i*4+3] = t.w;
        }
    }

    float o[32];
    #pragma unroll
    for (int d = 0; d < 32; d++) o[d] = 0.f;
    float mmax = -1e30f, l = 0.f;

    const float* kg = &g_k[(((b * HH) + h) * NN) * HD];
    const float* vg = &g_v[(((b * HH) + h) * NN) * HD];
    const int* rpg = &rp[(b * NN + chunk * 32) * NN];

    for (int j0 = 0; j0 < NN; j0 += 32) {
        __syncthreads();
        // Cooperative coalesced load of this head's k/v tile (32 keys x 32 d)
        #pragma unroll
        for (int i = 0; i < 8; i++) {
            int off = i * 128 + r * 4;
            *(float4*)&k_s[h * 1024 + off] = *(const float4*)&kg[j0 * HD + off];
            *(float4*)&v_s[h * 1024 + off] = *(const float4*)&vg[j0 * HD + off];
        }
        // Cooperative rp tile load (32 rows x 32 cols), shared across heads
        {
            int rr = tid >> 3, cc = (tid & 7) << 2;
            int4 t = *(const int4*)&rpg[rr * NN + j0 + cc];
            rp_s[rr * 33 + cc + 0] = t.x;
            rp_s[rr * 33 + cc + 1] = t.y;
            rp_s[rr * 33 + cc + 2] = t.z;
            rp_s[rr * 33 + cc + 3] = t.w;
        }
        __syncthreads();

        float s[32];
        float bm = -1e30f;
        #pragma unroll
        for (int j = 0; j < 32; j++) {
            float acc = 0.f;
            const float* kp = &k_s[h * 1024 + j * 32];
            #pragma unroll
            for (int d = 0; d < 32; d += 4) {
                float4 kv = *(float4*)&kp[d];
                acc += q[d]   * kv.x + q[d+1] * kv.y
                     + q[d+2] * kv.z + q[d+3] * kv.w;
            }
            int rpv = rp_s[r * 33 + j];
            float bias = bt_s[rpv * HH + h] + ((rpv > mask_len) ? -100.f : 0.f);
            s[j] = acc * scale + bias;
            bm = fmaxf(bm, s[j]);
        }

        float nm   = fmaxf(mmax, bm);
        float corr = __expf(mmax - nm);
        l *= corr;
        #pragma unroll
        for (int d = 0; d < 32; d++) o[d] *= corr;

        #pragma unroll
        for (int j = 0; j < 32; j++) {
            float p = __expf(s[j] - nm);
            l += p;
            const float* vp = &v_s[h * 1024 + j * 32];
            #pragma unroll
            for (int d = 0; d < 32; d += 4) {
                float4 vv = *(float4*)&vp[d];
                o[d]   += p * vv.x; o[d+1] += p * vv.y;
                o[d+2] += p * vv.z; o[d+3] += p * vv.w;
            }
        }
        mmax = nm;
    }

    float inv = 1.0f / l;
    float* xp = &g_x[(b * NN + row) * CC + h * HD];
    #pragma unroll
    for (int i = 0; i < 8; i++) {
        float4 t;
        t.x = o[i*4+0] * inv; t.y = o[i*4+1] * inv;
        t.z = o[i*4+2] * inv; t.w = o[i*4+3] * inv;
        *(float4*)&xp[i * 4] = t;
    }
}

// ---------------------------------------------------------------------------
// Kernel 3: output projection. g_x[8192,256] @ W[256,256] + b -> out
// ---------------------------------------------------------------------------
__global__ void __launch_bounds__(256) proj_gemm_kernel(
    const float* __restrict__ W, const float* __restrict__ bias,
    float* __restrict__ out)
{
    __shared__ float As[16][68];
    __shared__ float Bs[16][68];
    const int tid = threadIdx.x;
    const int tx = tid & 15, ty = tid >> 4;
    const int m0 = blockIdx.y * 64, n0 = blockIdx.x * 64;

    float acc[4][4];
    #pragma unroll
    for (int i = 0; i < 4; i++)
        #pragma unroll
        for (int j = 0; j < 4; j++) acc[i][j] = 0.f;

    for (int k0 = 0; k0 < 256; k0 += 16) {
        {
            int r  = tid >> 2;
            int kc = (tid & 3) << 2;
            float4 a = *(const float4*)&g_x[(m0 + r) * 256 + k0 + kc];
            As[kc+0][r] = a.x; As[kc+1][r] = a.y;
            As[kc+2][r] = a.z; As[kc+3][r] = a.w;
        }
        {
            int r2 = tid >> 4;
            int c  = (tid & 15) << 2;
            *(float4*)&Bs[r2][c] = *(const float4*)&W[(k0 + r2) * 256 + n0 + c];
        }
        __syncthreads();
        #pragma unroll
        for (int kk = 0; kk < 16; kk++) {
            float4 av = *(float4*)&As[kk][ty << 2];
            float4 bv = *(float4*)&Bs[kk][tx << 2];
            float a4[4] = {av.x, av.y, av.z, av.w};
            float b4[4] = {bv.x, bv.y, bv.z, bv.w};
            #pragma unroll
            for (int i = 0; i < 4; i++)
                #pragma unroll
                for (int j = 0; j < 4; j++) acc[i][j] += a4[i] * b4[j];
        }
        __syncthreads();
    }

    #pragma unroll
    for (int i = 0; i < 4; i++) {
        int m = m0 + (ty << 2) + i;
        #pragma unroll
        for (int j = 0; j < 4; j++) {
            int c = n0 + (tx << 2) + j;
            out[m * 256 + c] = acc[i][j] + bias[c];
        }
    }
}

// ---------------------------------------------------------------------------
extern "C" void kernel_launch(void* const* d_in, const int* in_sizes, int n_in,
                              void* d_out, int out_size)
{
    const float* X       = (const float*)d_in[0];  // att_embedding [B,N,C]
    const int*   rp      = (const int*)  d_in[1];  // relation_position [B,N,N]
    const int*   rel_len = (const int*)  d_in[2];  // [B]
    const float* Wqkv    = (const float*)d_in[3];  // [C,3C]
    const float* Wproj   = (const float*)d_in[4];  // [C,C]
    const float* bproj   = (const float*)d_in[5];  // [C]
    const float* btab    = (const float*)d_in[6];  // [TABLE,H]
    float* out = (float*)d_out;

    // 1) QKV projection + scatter
    {
        dim3 grid(768 / 64, (BB * NN) / 64);
        qkv_gemm_kernel<<<grid, 256>>>(X, Wqkv);
    }

    // 2) Fused attention
    {
        const int smem_bytes = (8*32*32 + 8*32*32) * 4 + 32*33*4 + TABLE*HH*4;
        cudaFuncSetAttribute(attn_kernel,
                             cudaFuncAttributeMaxDynamicSharedMemorySize,
                             smem_bytes);
        attn_kernel<<<BB * (NN / 32), 256, smem_bytes>>>(rp, rel_len, btab);
    }

    // 3) Output projection
    {
        dim3 grid(256 / 64, (BB * NN) / 64);
        proj_gemm_kernel<<<grid, 256>>>(Wproj, bproj, out);
    }
}

// round 2
// speedup vs baseline: 1.5219x; 1.5219x over previous
#include <cuda_runtime.h>
#include <cuda_bf16.h>
#include <cstdint>

#define BB 8
#define NN 1024
#define CC 256
#define HH 8
#define HD 32
#define TABLE 10

// Scratch (allocation-free rule: __device__ globals)
__device__ float g_q[BB*HH*NN*HD];
__device__ float g_k[BB*HH*NN*HD];
__device__ float g_v[BB*HH*NN*HD];
__device__ float g_x[BB*NN*CC];

// ---------------------------------------------------------------------------
// helpers
// ---------------------------------------------------------------------------
__device__ __forceinline__ uint32_t f2tf(float f) {
    uint32_t u;
    asm("cvt.rna.tf32.f32 %0, %1;" : "=r"(u) : "f"(f));
    return u;
}

__device__ __forceinline__ void mma16n8k8(float* c, const uint32_t* a, const uint32_t* b) {
    asm volatile(
        "mma.sync.aligned.m16n8k8.row.col.f32.tf32.tf32.f32 "
        "{%0,%1,%2,%3},{%4,%5,%6,%7},{%8,%9},{%0,%1,%2,%3};\n"
        : "+f"(c[0]), "+f"(c[1]), "+f"(c[2]), "+f"(c[3])
        : "r"(a[0]), "r"(a[1]), "r"(a[2]), "r"(a[3]), "r"(b[0]), "r"(b[1]));
}

// ---------------------------------------------------------------------------
// Kernel 1: QKV projection. X[8192,256] @ W[256,768] -> scatter q/k/v [B,H,N,hd]
// ---------------------------------------------------------------------------
__global__ void __launch_bounds__(256) qkv_gemm_kernel(
    const float* __restrict__ X, const float* __restrict__ W)
{
    __shared__ float As[16][68];
    __shared__ float Bs[16][68];
    const int tid = threadIdx.x;
    const int tx = tid & 15, ty = tid >> 4;
    const int m0 = blockIdx.y * 64, n0 = blockIdx.x * 64;

    float acc[4][4];
    #pragma unroll
    for (int i = 0; i < 4; i++)
        #pragma unroll
        for (int j = 0; j < 4; j++) acc[i][j] = 0.f;

    for (int k0 = 0; k0 < 256; k0 += 16) {
        {
            int r  = tid >> 2;
            int kc = (tid & 3) << 2;
            float4 a = *(const float4*)&X[(m0 + r) * 256 + k0 + kc];
            As[kc+0][r] = a.x; As[kc+1][r] = a.y;
            As[kc+2][r] = a.z; As[kc+3][r] = a.w;
        }
        {
            int r2 = tid >> 4;
            int c  = (tid & 15) << 2;
            *(float4*)&Bs[r2][c] = *(const float4*)&W[(k0 + r2) * 768 + n0 + c];
        }
        __syncthreads();
        #pragma unroll
        for (int kk = 0; kk < 16; kk++) {
            float4 av = *(float4*)&As[kk][ty << 2];
            float4 bv = *(float4*)&Bs[kk][tx << 2];
            float a4[4] = {av.x, av.y, av.z, av.w};
            float b4[4] = {bv.x, bv.y, bv.z, bv.w};
            #pragma unroll
            for (int i = 0; i < 4; i++)
                #pragma unroll
                for (int j = 0; j < 4; j++) acc[i][j] += a4[i] * b4[j];
        }
        __syncthreads();
    }

    #pragma unroll
    for (int i = 0; i < 4; i++) {
        int m = m0 + (ty << 2) + i;
        int b = m >> 10, n = m & 1023;
        #pragma unroll
        for (int j = 0; j < 4; j++) {
            int c   = n0 + (tx << 2) + j;
            int sel = c >> 8;
            int h   = (c & 255) >> 5;
            int d   = c & 31;
            float* dst = (sel == 0) ? g_q : ((sel == 1) ? g_k : g_v);
            dst[(((b * HH) + h) * NN + n) * HD + d] = acc[i][j];
        }
    }
}

// ---------------------------------------------------------------------------
// Kernel 2: fused flash attention, tf32 tensor cores (mma.sync m16n8k8).
// Block = (batch, 32 query rows). 8 warps = 8 heads (rp tile shared once).
// Per warp: 2 m-tiles (16 rows each) x 1024 keys in 32-key tiles.
// ---------------------------------------------------------------------------
#define KS_STRIDE 36   // K/V smem row stride (words): conflict-free K b-frags, 16B aligned
#define PS_STRIDE 34   // P smem row stride (words): 8B aligned for uint2 stores

__global__ void __launch_bounds__(256, 2) attn_mma_kernel(
    const int* __restrict__ rp, const int* __restrict__ rel_len,
    const float* __restrict__ bias_table)
{
    extern __shared__ uint32_t sm[];
    uint32_t* k_s  = sm;                          // [8][32][36] tf32 bits
    uint32_t* v_s  = k_s + 8 * 32 * KS_STRIDE;    // [8][32][36]
    uint32_t* p_s  = v_s + 8 * 32 * KS_STRIDE;    // [8 warps][32][34]
    int*      rp_s = (int*)(p_s + 8 * 32 * PS_STRIDE);  // [32][33]

    const int tid  = threadIdx.x;
    const int warp = tid >> 5;
    const int lane = tid & 31;
    const int h    = warp;
    const int g    = lane >> 2;      // groupID (row within m16)
    const int t    = lane & 3;       // thread-in-group
    const int b    = blockIdx.x >> 5;
    const int row0 = (blockIdx.x & 31) * 32;

    // Per-head masked bias table, held in lane registers (shfl lookup)
    const int mask_len = (int)(__int2float_rn(rel_len[b]) * 0.5f);
    float bt2 = 0.f;
    if (lane < TABLE)
        bt2 = bias_table[lane * HH + h] + ((lane > mask_len) ? -100.f : 0.f);

    uint32_t* pw = p_s + warp * (32 * PS_STRIDE);

    // ---- Q fragments (scaled, tf32), staged through p_s ----
    uint32_t qa[2][4][4];   // [m-tile][k-step][reg]
    {
        const float scale = 0.17677669529663687f;  // 32^-0.5
        const float* qg = &g_q[(((long)(b * HH) + h) * NN + row0) * HD];
        #pragma unroll
        for (int i = 0; i < 8; i++) {
            float4 v4 = *(const float4*)&qg[lane * HD + i * 4];
            uint32_t* d = &pw[lane * PS_STRIDE + i * 4];
            d[0] = f2tf(v4.x * scale); d[1] = f2tf(v4.y * scale);
            d[2] = f2tf(v4.z * scale); d[3] = f2tf(v4.w * scale);
        }
        __syncwarp();
        #pragma unroll
        for (int mt = 0; mt < 2; mt++) {
            int rA = mt * 16 + g;
            #pragma unroll
            for (int ks = 0; ks < 4; ks++) {
                qa[mt][ks][0] = pw[rA * PS_STRIDE + ks * 8 + t];
                qa[mt][ks][1] = pw[(rA + 8) * PS_STRIDE + ks * 8 + t];
                qa[mt][ks][2] = pw[rA * PS_STRIDE + ks * 8 + t + 4];
                qa[mt][ks][3] = pw[(rA + 8) * PS_STRIDE + ks * 8 + t + 4];
            }
        }
    }

    float o[2][4][4];
    #pragma unroll
    for (int mt = 0; mt < 2; mt++)
        #pragma unroll
        for (int nt = 0; nt < 4; nt++)
            #pragma unroll
            for (int r = 0; r < 4; r++) o[mt][nt][r] = 0.f;
    float mrow[2][2] = {{-1e30f, -1e30f}, {-1e30f, -1e30f}};
    float lrow[2][2] = {{0.f, 0.f}, {0.f, 0.f}};

    const uint32_t* kh = &k_s[h * 32 * KS_STRIDE];
    const uint32_t* vh = &v_s[h * 32 * KS_STRIDE];

    for (int j0 = 0; j0 < NN; j0 += 32) {
        __syncthreads();
        // ---- cooperative K/V tile load (all 8 heads), convert to tf32 ----
        #pragma unroll
        for (int it = 0; it < 8; it++) {
            int idx = it * 256 + tid;            // float4 units, 2048 total
            int h2  = idx >> 8;
            int key = (idx >> 3) & 31;
            int d4  = (idx & 7) * 4;
            long off = (((long)(b * HH + h2)) * NN + j0 + key) * HD + d4;
            float4 kv = *(const float4*)&g_k[off];
            float4 vv = *(const float4*)&g_v[off];
            uint32_t* kd = &k_s[(h2 * 32 + key) * KS_STRIDE + d4];
            uint32_t* vd = &v_s[(h2 * 32 + key) * KS_STRIDE + d4];
            *(uint4*)kd = make_uint4(f2tf(kv.x), f2tf(kv.y), f2tf(kv.z), f2tf(kv.w));
            *(uint4*)vd = make_uint4(f2tf(vv.x), f2tf(vv.y), f2tf(vv.z), f2tf(vv.w));
        }
        // ---- rp tile (32 x 32), shared across all heads ----
        {
            int rr = tid >> 3, cc = (tid & 7) * 4;
            int4 rv = *(const int4*)&rp[((long)b * NN + row0 + rr) * NN + j0 + cc];
            rp_s[rr * 33 + cc + 0] = rv.x;
            rp_s[rr * 33 + cc + 1] = rv.y;
            rp_s[rr * 33 + cc + 2] = rv.z;
            rp_s[rr * 33 + cc + 3] = rv.w;
        }
        __syncthreads();

        // ---- S = Q @ K^T  (scale pre-folded into Q) ----
        float c[2][4][4];
        #pragma unroll
        for (int mt = 0; mt < 2; mt++)
            #pragma unroll
            for (int nt = 0; nt < 4; nt++)
                #pragma unroll
                for (int r = 0; r < 4; r++) c[mt][nt][r] = 0.f;

        #pragma unroll
        for (int nt = 0; nt < 4; nt++)
            #pragma unroll
            for (int ks = 0; ks < 4; ks++) {
                uint32_t bf[2];
                bf[0] = kh[(nt * 8 + g) * KS_STRIDE + ks * 8 + t];
                bf[1] = kh[(nt * 8 + g) * KS_STRIDE + ks * 8 + t + 4];
                mma16n8k8(c[0][nt], qa[0][ks], bf);
                mma16n8k8(c[1][nt], qa[1][ks], bf);
            }

        // ---- bias + online softmax + store P (tf32) ----
        #pragma unroll
        for (int mt = 0; mt < 2; mt++) {
            int rA = mt * 16 + g;
            int rB = rA + 8;
            float mx0 = -1e30f, mx1 = -1e30f;
            #pragma unroll
            for (int nt = 0; nt < 4; nt++) {
                int colb = nt * 8 + 2 * t;
                int r00 = rp_s[rA * 33 + colb], r01 = rp_s[rA * 33 + colb + 1];
                int r10 = rp_s[rB * 33 + colb], r11 = rp_s[rB * 33 + colb + 1];
                c[mt][nt][0] += __shfl_sync(0xffffffffu, bt2, r00);
                c[mt][nt][1] += __shfl_sync(0xffffffffu, bt2, r01);
                c[mt][nt][2] += __shfl_sync(0xffffffffu, bt2, r10);
                c[mt][nt][3] += __shfl_sync(0xffffffffu, bt2, r11);
                mx0 = fmaxf(mx0, fmaxf(c[mt][nt][0], c[mt][nt][1]));
                mx1 = fmaxf(mx1, fmaxf(c[mt][nt][2], c[mt][nt][3]));
            }
            mx0 = fmaxf(mx0, __shfl_xor_sync(0xffffffffu, mx0, 1));
            mx0 = fmaxf(mx0, __shfl_xor_sync(0xffffffffu, mx0, 2));
            mx1 = fmaxf(mx1, __shfl_xor_sync(0xffffffffu, mx1, 1));
            mx1 = fmaxf(mx1, __shfl_xor_sync(0xffffffffu, mx1, 2));

            float nm0 = fmaxf(mrow[mt][0], mx0);
            float nm1 = fmaxf(mrow[mt][1], mx1);
            float corr0 = __expf(mrow[mt][0] - nm0);
            float corr1 = __expf(mrow[mt][1] - nm1);
            float rs0 = 0.f, rs1 = 0.f;
            #pragma unroll
            for (int nt = 0; nt < 4; nt++) {
                float p0 = __expf(c[mt][nt][0] - nm0);
                float p1 = __expf(c[mt][nt][1] - nm0);
                float p2 = __expf(c[mt][nt][2] - nm1);
                float p3 = __expf(c[mt][nt][3] - nm1);
                rs0 += p0 + p1;
                rs1 += p2 + p3;
                *(uint2*)&pw[rA * PS_STRIDE + nt * 8 + 2 * t] = make_uint2(f2tf(p0), f2tf(p1));
                *(uint2*)&pw[rB * PS_STRIDE + nt * 8 + 2 * t] = make_uint2(f2tf(p2), f2tf(p3));
            }
            rs0 += __shfl_xor_sync(0xffffffffu, rs0, 1);
            rs0 += __shfl_xor_sync(0xffffffffu, rs0, 2);
            rs1 += __shfl_xor_sync(0xffffffffu, rs1, 1);
            rs1 += __shfl_xor_sync(0xffffffffu, rs1, 2);
            lrow[mt][0] = lrow[mt][0] * corr0 + rs0;
            lrow[mt][1] = lrow[mt][1] * corr1 + rs1;
            #pragma unroll
            for (int nt = 0; nt < 4; nt++) {
                o[mt][nt][0] *= corr0; o[mt][nt][1] *= corr0;
                o[mt][nt][2] *= corr1; o[mt][nt][3] *= corr1;
            }
            mrow[mt][0] = nm0;
            mrow[mt][1] = nm1;
        }
        __syncwarp();

        // ---- O += P @ V ----
        #pragma unroll
        for (int ks = 0; ks < 4; ks++) {
            uint32_t a[2][4];
            #pragma unroll
            for (int mt = 0; mt < 2; mt++) {
                int rA = mt * 16 + g;
                a[mt][0] = pw[rA * PS_STRIDE + ks * 8 + t];
                a[mt][1] = pw[(rA + 8) * PS_STRIDE + ks * 8 + t];
                a[mt][2] = pw[rA * PS_STRIDE + ks * 8 + t + 4];
                a[mt][3] = pw[(rA + 8) * PS_STRIDE + ks * 8 + t + 4];
            }
            #pragma unroll
            for (int nt = 0; nt < 4; nt++) {
                uint32_t bf[2];
                bf[0] = vh[(ks * 8 + t) * KS_STRIDE + nt * 8 + g];
                bf[1] = vh[(ks * 8 + t + 4) * KS_STRIDE + nt * 8 + g];
                mma16n8k8(o[0][nt], a[0], bf);
                mma16n8k8(o[1][nt], a[1], bf);
            }
        }
    }

    // ---- epilogue: normalize, store to g_x ----
    #pragma unroll
    for (int mt = 0; mt < 2; mt++) {
        float i0 = 1.f / lrow[mt][0];
        float i1 = 1.f / lrow[mt][1];
        int rA = row0 + mt * 16 + g;
        #pragma unroll
        for (int nt = 0; nt < 4; nt++) {
            int col = h * HD + nt * 8 + 2 * t;
            float2 w0 = make_float2(o[mt][nt][0] * i0, o[mt][nt][1] * i0);
            float2 w1 = make_float2(o[mt][nt][2] * i1, o[mt][nt][3] * i1);
            *(float2*)&g_x[((long)b * NN + rA) * CC + col]     = w0;
            *(float2*)&g_x[((long)b * NN + rA + 8) * CC + col] = w1;
        }
    }
}

// ---------------------------------------------------------------------------
// Kernel 3: output projection. g_x[8192,256] @ W[256,256] + b -> out
// ---------------------------------------------------------------------------
__global__ void __launch_bounds__(256) proj_gemm_kernel(
    const float* __restrict__ W, const float* __restrict__ bias,
    float* __restrict__ out)
{
    __shared__ float As[16][68];
    __shared__ float Bs[16][68];
    const int tid = threadIdx.x;
    const int tx = tid & 15, ty = tid >> 4;
    const int m0 = blockIdx.y * 64, n0 = blockIdx.x * 64;

    float acc[4][4];
    #pragma unroll
    for (int i = 0; i < 4; i++)
        #pragma unroll
        for (int j = 0; j < 4; j++) acc[i][j] = 0.f;

    for (int k0 = 0; k0 < 256; k0 += 16) {
        {
            int r  = tid >> 2;
            int kc = (tid & 3) << 2;
            float4 a = *(const float4*)&g_x[(m0 + r) * 256 + k0 + kc];
            As[kc+0][r] = a.x; As[kc+1][r] = a.y;
            As[kc+2][r] = a.z; As[kc+3][r] = a.w;
        }
        {
            int r2 = tid >> 4;
            int c  = (tid & 15) << 2;
            *(float4*)&Bs[r2][c] = *(const float4*)&W[(k0 + r2) * 256 + n0 + c];
        }
        __syncthreads();
        #pragma unroll
        for (int kk = 0; kk < 16; kk++) {
            float4 av = *(float4*)&As[kk][ty << 2];
            float4 bv = *(float4*)&Bs[kk][tx << 2];
            float a4[4] = {av.x, av.y, av.z, av.w};
            float b4[4] = {bv.x, bv.y, bv.z, bv.w};
            #pragma unroll
            for (int i = 0; i < 4; i++)
                #pragma unroll
                for (int j = 0; j < 4; j++) acc[i][j] += a4[i] * b4[j];
        }
        __syncthreads();
    }

    #pragma unroll
    for (int i = 0; i < 4; i++) {
        int m = m0 + (ty << 2) + i;
        #pragma unroll
        for (int j = 0; j < 4; j++) {
            int c = n0 + (tx << 2) + j;
            out[m * 256 + c] = acc[i][j] + bias[c];
        }
    }
}

// ---------------------------------------------------------------------------
extern "C" void kernel_launch(void* const* d_in, const int* in_sizes, int n_in,
                              void* d_out, int out_size)
{
    const float* X       = (const float*)d_in[0];
    const int*   rp      = (const int*)  d_in[1];
    const int*   rel_len = (const int*)  d_in[2];
    const float* Wqkv    = (const float*)d_in[3];
    const float* Wproj   = (const float*)d_in[4];
    const float* bproj   = (const float*)d_in[5];
    const float* btab    = (const float*)d_in[6];
    float* out = (float*)d_out;

    {
        dim3 grid(768 / 64, (BB * NN) / 64);
        qkv_gemm_kernel<<<grid, 256>>>(X, Wqkv);
    }

    {
        const int smem_bytes =
            (8*32*KS_STRIDE * 2 + 8*32*PS_STRIDE) * 4 + 32*33*4;
        static int configured = 0;
        // cudaFuncSetAttribute every call is graph-capture-safe (host-side, no alloc)
        cudaFuncSetAttribute(attn_mma_kernel,
                             cudaFuncAttributeMaxDynamicSharedMemorySize,
                             smem_bytes);
        (void)configured;
        attn_mma_kernel<<<BB * 32, 256, smem_bytes>>>(rp, rel_len, btab);
    }

    {
        dim3 grid(256 / 64, (BB * NN) / 64);
        proj_gemm_kernel<<<grid, 256>>>(Wproj, bproj, out);
    }
}

// round 3
// speedup vs baseline: 1.9691x; 1.2939x over previous
#include <cuda_runtime.h>
#include <cuda_fp16.h>
#include <cstdint>

#define BB 8
#define NN 1024
#define CC 256
#define HH 8
#define HD 32
#define TABLE 10

// Scratch (allocation-free rule: __device__ globals)
__device__ __half g_qh[BB*HH*NN*HD];   // pre-scaled q, fp16
__device__ __half g_kh[BB*HH*NN*HD];   // fp16
__device__ __half g_vh[BB*HH*NN*HD];   // fp16
__device__ float  g_x [BB*NN*CC];

// ---------------------------------------------------------------------------
// helpers
// ---------------------------------------------------------------------------
__device__ __forceinline__ void mma_f16(float* c, const uint32_t* a, const uint32_t* b) {
    asm volatile(
        "mma.sync.aligned.m16n8k16.row.col.f32.f16.f16.f32 "
        "{%0,%1,%2,%3},{%4,%5,%6,%7},{%8,%9},{%0,%1,%2,%3};\n"
        : "+f"(c[0]), "+f"(c[1]), "+f"(c[2]), "+f"(c[3])
        : "r"(a[0]), "r"(a[1]), "r"(a[2]), "r"(a[3]), "r"(b[0]), "r"(b[1]));
}
// pack two floats into half2 bits: low half = lo, high half = hi
__device__ __forceinline__ uint32_t h2pack(float lo, float hi) {
    __half2 h = __floats2half2_rn(lo, hi);
    return *(uint32_t*)&h;
}
__device__ __forceinline__ uint32_t prmt(uint32_t a, uint32_t b, uint32_t s) {
    uint32_t d;
    asm("prmt.b32 %0,%1,%2,%3;" : "=r"(d) : "r"(a), "r"(b), "r"(s));
    return d;
}

// ---------------------------------------------------------------------------
// Kernel 1: QKV projection. X[8192,256] @ W[256,768] -> q(scaled)/k/v fp16
// ---------------------------------------------------------------------------
__global__ void __launch_bounds__(256) qkv_gemm_kernel(
    const float* __restrict__ X, const float* __restrict__ W)
{
    __shared__ float As[16][68];
    __shared__ float Bs[16][68];
    const int tid = threadIdx.x;
    const int tx = tid & 15, ty = tid >> 4;
    const int m0 = blockIdx.y * 64, n0 = blockIdx.x * 64;

    float acc[4][4];
    #pragma unroll
    for (int i = 0; i < 4; i++)
        #pragma unroll
        for (int j = 0; j < 4; j++) acc[i][j] = 0.f;

    for (int k0 = 0; k0 < 256; k0 += 16) {
        {
            int r  = tid >> 2;
            int kc = (tid & 3) << 2;
            float4 a = *(const float4*)&X[(m0 + r) * 256 + k0 + kc];
            As[kc+0][r] = a.x; As[kc+1][r] = a.y;
            As[kc+2][r] = a.z; As[kc+3][r] = a.w;
        }
        {
            int r2 = tid >> 4;
            int c  = (tid & 15) << 2;
            *(float4*)&Bs[r2][c] = *(const float4*)&W[(k0 + r2) * 768 + n0 + c];
        }
        __syncthreads();
        #pragma unroll
        for (int kk = 0; kk < 16; kk++) {
            float4 av = *(float4*)&As[kk][ty << 2];
            float4 bv = *(float4*)&Bs[kk][tx << 2];
            float a4[4] = {av.x, av.y, av.z, av.w};
            float b4[4] = {bv.x, bv.y, bv.z, bv.w};
            #pragma unroll
            for (int i = 0; i < 4; i++)
                #pragma unroll
                for (int j = 0; j < 4; j++) acc[i][j] += a4[i] * b4[j];
        }
        __syncthreads();
    }

    const float scale = 0.17677669529663687f;   // 32^-0.5 folded into q
    #pragma unroll
    for (int i = 0; i < 4; i++) {
        int m = m0 + (ty << 2) + i;
        int b = m >> 10, n = m & 1023;
        #pragma unroll
        for (int j = 0; j < 4; j++) {
            int c   = n0 + (tx << 2) + j;
            int sel = c >> 8;
            int h   = (c & 255) >> 5;
            int d   = c & 31;
            long idx = (((long)(b * HH) + h) * NN + n) * HD + d;
            if (sel == 0)      g_qh[idx] = __float2half_rn(acc[i][j] * scale);
            else if (sel == 1) g_kh[idx] = __float2half_rn(acc[i][j]);
            else               g_vh[idx] = __float2half_rn(acc[i][j]);
        }
    }
}

// ---------------------------------------------------------------------------
// Kernel 2: fused flash attention, fp16 mma.m16n8k16.
// Block = (batch, 32 query rows). 8 warps = 8 heads (rp tile shared once).
// P stays in registers (C-frag == A-frag pair layout).
// ---------------------------------------------------------------------------
#define KP_STRIDE 40   // words per row of kp_s / vp_s (32 data + 8 pad)

__global__ void __launch_bounds__(256, 2) attn_mma_kernel(
    const int* __restrict__ rp, const int* __restrict__ rel_len,
    const float* __restrict__ bias_table)
{
    extern __shared__ uint32_t sm[];
    uint32_t* kp_s = sm;                           // [8][16][40]: {K[key][2d2],K[key][2d2+1]} at [h][d2][key]
    uint32_t* vp_s = kp_s + 8 * 16 * KP_STRIDE;    // [8][16][40]: {V[2k2][d],V[2k2+1][d]}   at [h][k2][d]
    int*      rp_s = (int*)(vp_s + 8 * 16 * KP_STRIDE);  // [32][33]

    const int tid  = threadIdx.x;
    const int h    = tid >> 5;       // warp = head
    const int lane = tid & 31;
    const int g    = lane >> 2;      // groupID
    const int t    = lane & 3;       // thread-in-group
    const int b    = blockIdx.x >> 5;
    const int row0 = (blockIdx.x & 31) * 32;

    // Per-head masked bias table in lane registers (shfl lookup)
    const int mask_len = (int)(__int2float_rn(rel_len[b]) * 0.5f);
    float bt2 = 0.f;
    if (lane < TABLE)
        bt2 = bias_table[lane * HH + h] + ((lane > mask_len) ? -100.f : 0.f);

    // ---- Q fragments (fp16, pre-scaled): direct loads from g_qh ----
    uint32_t qa[2][2][4];   // [m-tile][k-step(16)][reg]
    {
        const uint32_t* qw = (const uint32_t*)g_qh;
        long rbase = ((long)(b * HH) + h) * NN + row0;
        #pragma unroll
        for (int mt = 0; mt < 2; mt++) {
            long rA = (rbase + mt * 16 + g) * 16;       // 16 words/row
            long rB = rA + 8 * 16;
            #pragma unroll
            for (int ks = 0; ks < 2; ks++) {
                int w = ks * 8 + t;
                qa[mt][ks][0] = qw[rA + w];
                qa[mt][ks][1] = qw[rB + w];
                qa[mt][ks][2] = qw[rA + w + 4];
                qa[mt][ks][3] = qw[rB + w + 4];
            }
        }
    }

    float o[2][4][4];
    #pragma unroll
    for (int mt = 0; mt < 2; mt++)
        #pragma unroll
        for (int nt = 0; nt < 4; nt++)
            #pragma unroll
            for (int r = 0; r < 4; r++) o[mt][nt][r] = 0.f;
    float mrow[2][2] = {{-1e30f, -1e30f}, {-1e30f, -1e30f}};
    float lrow[2][2] = {{0.f, 0.f}, {0.f, 0.f}};

    const uint32_t* kh = &kp_s[h * 16 * KP_STRIDE];
    const uint32_t* vh = &vp_s[h * 16 * KP_STRIDE];
    const __half* gk = g_kh;
    const __half* gv = g_vh;

    for (int j0 = 0; j0 < NN; j0 += 32) {
        __syncthreads();
        // ---- K tiles: raw uint4 copy, smem = transpose of half2-word matrix ----
        #pragma unroll
        for (int it = 0; it < 4; it++) {
            int idx = it * 256 + tid;        // 1024 slots: 8h x 32key x 4quads
            int key = idx & 31;
            int q4  = (idx >> 5) & 3;
            int h2  = idx >> 7;
            long base = (((long)(b * HH + h2)) * NN + j0 + key) * 32;
            uint4 kw = *(const uint4*)(gk + base + q4 * 8);
            uint32_t* col = &kp_s[h2 * (16 * KP_STRIDE) + (q4 * 4) * KP_STRIDE + key];
            col[0 * KP_STRIDE] = kw.x;
            col[1 * KP_STRIDE] = kw.y;
            col[2 * KP_STRIDE] = kw.z;
            col[3 * KP_STRIDE] = kw.w;
        }
        // ---- V tiles: interleave adjacent-key pairs via prmt ----
        #pragma unroll
        for (int it = 0; it < 2; it++) {
            int idx = it * 256 + tid;        // 512 slots: 8h x 16key2 x 4 d-groups
            int d4   = idx & 3;
            int key2 = (idx >> 2) & 15;
            int h2   = idx >> 6;
            long base = (((long)(b * HH + h2)) * NN + j0 + 2 * key2) * 32;
            uint4 v0 = *(const uint4*)(gv + base + d4 * 8);
            uint4 v1 = *(const uint4*)(gv + base + 32 + d4 * 8);
            uint32_t* dst = &vp_s[h2 * (16 * KP_STRIDE) + key2 * KP_STRIDE + d4 * 8];
            *(uint4*)dst = make_uint4(
                prmt(v0.x, v1.x, 0x5410), prmt(v0.x, v1.x, 0x7632),
                prmt(v0.y, v1.y, 0x5410), prmt(v0.y, v1.y, 0x7632));
            *(uint4*)(dst + 4) = make_uint4(
                prmt(v0.z, v1.z, 0x5410), prmt(v0.z, v1.z, 0x7632),
                prmt(v0.w, v1.w, 0x5410), prmt(v0.w, v1.w, 0x7632));
        }
        // ---- rp tile (32 x 32), shared across all heads ----
        {
            int rr = tid >> 3, cc = (tid & 7) * 4;
            int4 rv = *(const int4*)&rp[((long)b * NN + row0 + rr) * NN + j0 + cc];
            rp_s[rr * 33 + cc + 0] = rv.x;
            rp_s[rr * 33 + cc + 1] = rv.y;
            rp_s[rr * 33 + cc + 2] = rv.z;
            rp_s[rr * 33 + cc + 3] = rv.w;
        }
        __syncthreads();

        // ---- S = Q @ K^T (scale pre-folded into q) ----
        float c[2][4][4];
        #pragma unroll
        for (int mt = 0; mt < 2; mt++)
            #pragma unroll
            for (int nt = 0; nt < 4; nt++)
                #pragma unroll
                for (int r = 0; r < 4; r++) c[mt][nt][r] = 0.f;

        #pragma unroll
        for (int nt = 0; nt < 4; nt++)
            #pragma unroll
            for (int ks = 0; ks < 2; ks++) {
                uint32_t bf[2];
                bf[0] = kh[(ks * 8 + t) * KP_STRIDE + nt * 8 + g];
                bf[1] = kh[(ks * 8 + t + 4) * KP_STRIDE + nt * 8 + g];
                mma_f16(c[0][nt], qa[0][ks], bf);
                mma_f16(c[1][nt], qa[1][ks], bf);
            }

        // ---- bias + online softmax (on C-frags) ----
        #pragma unroll
        for (int mt = 0; mt < 2; mt++) {
            int rA = mt * 16 + g;
            int rB = rA + 8;
            float mx0 = -1e30f, mx1 = -1e30f;
            #pragma unroll
            for (int nt = 0; nt < 4; nt++) {
                int colb = nt * 8 + 2 * t;
                int r00 = rp_s[rA * 33 + colb], r01 = rp_s[rA * 33 + colb + 1];
                int r10 = rp_s[rB * 33 + colb], r11 = rp_s[rB * 33 + colb + 1];
                c[mt][nt][0] += __shfl_sync(0xffffffffu, bt2, r00);
                c[mt][nt][1] += __shfl_sync(0xffffffffu, bt2, r01);
                c[mt][nt][2] += __shfl_sync(0xffffffffu, bt2, r10);
                c[mt][nt][3] += __shfl_sync(0xffffffffu, bt2, r11);
                mx0 = fmaxf(mx0, fmaxf(c[mt][nt][0], c[mt][nt][1]));
                mx1 = fmaxf(mx1, fmaxf(c[mt][nt][2], c[mt][nt][3]));
            }
            mx0 = fmaxf(mx0, __shfl_xor_sync(0xffffffffu, mx0, 1));
            mx0 = fmaxf(mx0, __shfl_xor_sync(0xffffffffu, mx0, 2));
            mx1 = fmaxf(mx1, __shfl_xor_sync(0xffffffffu, mx1, 1));
            mx1 = fmaxf(mx1, __shfl_xor_sync(0xffffffffu, mx1, 2));

            float nm0 = fmaxf(mrow[mt][0], mx0);
            float nm1 = fmaxf(mrow[mt][1], mx1);
            float corr0 = __expf(mrow[mt][0] - nm0);
            float corr1 = __expf(mrow[mt][1] - nm1);
            float rs0 = 0.f, rs1 = 0.f;
            #pragma unroll
            for (int nt = 0; nt < 4; nt++) {
                c[mt][nt][0] = __expf(c[mt][nt][0] - nm0);
                c[mt][nt][1] = __expf(c[mt][nt][1] - nm0);
                c[mt][nt][2] = __expf(c[mt][nt][2] - nm1);
                c[mt][nt][3] = __expf(c[mt][nt][3] - nm1);
                rs0 += c[mt][nt][0] + c[mt][nt][1];
                rs1 += c[mt][nt][2] + c[mt][nt][3];
            }
            rs0 += __shfl_xor_sync(0xffffffffu, rs0, 1);
            rs0 += __shfl_xor_sync(0xffffffffu, rs0, 2);
            rs1 += __shfl_xor_sync(0xffffffffu, rs1, 1);
            rs1 += __shfl_xor_sync(0xffffffffu, rs1, 2);
            lrow[mt][0] = lrow[mt][0] * corr0 + rs0;
            lrow[mt][1] = lrow[mt][1] * corr1 + rs1;
            #pragma unroll
            for (int nt = 0; nt < 4; nt++) {
                o[mt][nt][0] *= corr0; o[mt][nt][1] *= corr0;
                o[mt][nt][2] *= corr1; o[mt][nt][3] *= corr1;
            }
            mrow[mt][0] = nm0;
            mrow[mt][1] = nm1;
        }

        // ---- P: C-frag -> A-frag in registers (no smem round trip) ----
        uint32_t pa[2][2][4];
        #pragma unroll
        for (int mt = 0; mt < 2; mt++)
            #pragma unroll
            for (int ks = 0; ks < 2; ks++) {
                pa[mt][ks][0] = h2pack(c[mt][2*ks  ][0], c[mt][2*ks  ][1]);
                pa[mt][ks][1] = h2pack(c[mt][2*ks  ][2], c[mt][2*ks  ][3]);
                pa[mt][ks][2] = h2pack(c[mt][2*ks+1][0], c[mt][2*ks+1][1]);
                pa[mt][ks][3] = h2pack(c[mt][2*ks+1][2], c[mt][2*ks+1][3]);
            }

        // ---- O += P @ V ----
        #pragma unroll
        for (int ks = 0; ks < 2; ks++)
            #pragma unroll
            for (int nt = 0; nt < 4; nt++) {
                uint32_t bf[2];
                bf[0] = vh[(ks * 8 + t) * KP_STRIDE + nt * 8 + g];
                bf[1] = vh[(ks * 8 + t + 4) * KP_STRIDE + nt * 8 + g];
                mma_f16(o[0][nt], pa[0][ks], bf);
                mma_f16(o[1][nt], pa[1][ks], bf);
            }
    }

    // ---- epilogue: normalize, store to g_x ----
    #pragma unroll
    for (int mt = 0; mt < 2; mt++) {
        float i0 = 1.f / lrow[mt][0];
        float i1 = 1.f / lrow[mt][1];
        int rA = row0 + mt * 16 + g;
        #pragma unroll
        for (int nt = 0; nt < 4; nt++) {
            int col = h * HD + nt * 8 + 2 * t;
            float2 w0 = make_float2(o[mt][nt][0] * i0, o[mt][nt][1] * i0);
            float2 w1 = make_float2(o[mt][nt][2] * i1, o[mt][nt][3] * i1);
            *(float2*)&g_x[((long)b * NN + rA) * CC + col]     = w0;
            *(float2*)&g_x[((long)b * NN + rA + 8) * CC + col] = w1;
        }
    }
}

// ---------------------------------------------------------------------------
// Kernel 3: output projection. g_x[8192,256] @ W[256,256] + b -> out
// ---------------------------------------------------------------------------
__global__ void __launch_bounds__(256) proj_gemm_kernel(
    const float* __restrict__ W, const float* __restrict__ bias,
    float* __restrict__ out)
{
    __shared__ float As[16][68];
    __shared__ float Bs[16][68];
    const int tid = threadIdx.x;
    const int tx = tid & 15, ty = tid >> 4;
    const int m0 = blockIdx.y * 64, n0 = blockIdx.x * 64;

    float acc[4][4];
    #pragma unroll
    for (int i = 0; i < 4; i++)
        #pragma unroll
        for (int j = 0; j < 4; j++) acc[i][j] = 0.f;

    for (int k0 = 0; k0 < 256; k0 += 16) {
        {
            int r  = tid >> 2;
            int kc = (tid & 3) << 2;
            float4 a = *(const float4*)&g_x[(m0 + r) * 256 + k0 + kc];
            As[kc+0][r] = a.x; As[kc+1][r] = a.y;
            As[kc+2][r] = a.z; As[kc+3][r] = a.w;
        }
        {
            int r2 = tid >> 4;
            int c  = (tid & 15) << 2;
            *(float4*)&Bs[r2][c] = *(const float4*)&W[(k0 + r2) * 256 + n0 + c];
        }
        __syncthreads();
        #pragma unroll
        for (int kk = 0; kk < 16; kk++) {
            float4 av = *(float4*)&As[kk][ty << 2];
            float4 bv = *(float4*)&Bs[kk][tx << 2];
            float a4[4] = {av.x, av.y, av.z, av.w};
            float b4[4] = {bv.x, bv.y, bv.z, bv.w};
            #pragma unroll
            for (int i = 0; i < 4; i++)
                #pragma unroll
                for (int j = 0; j < 4; j++) acc[i][j] += a4[i] * b4[j];
        }
        __syncthreads();
    }

    #pragma unroll
    for (int i = 0; i < 4; i++) {
        int m = m0 + (ty << 2) + i;
        #pragma unroll
        for (int j = 0; j < 4; j++) {
            int c = n0 + (tx << 2) + j;
            out[m * 256 + c] = acc[i][j] + bias[c];
        }
    }
}

// ---------------------------------------------------------------------------
extern "C" void kernel_launch(void* const* d_in, const int* in_sizes, int n_in,
                              void* d_out, int out_size)
{
    const float* X       = (const float*)d_in[0];
    const int*   rp      = (const int*)  d_in[1];
    const int*   rel_len = (const int*)  d_in[2];
    const float* Wqkv    = (const float*)d_in[3];
    const float* Wproj   = (const float*)d_in[4];
    const float* bproj   = (const float*)d_in[5];
    const float* btab    = (const float*)d_in[6];
    float* out = (float*)d_out;

    {
        dim3 grid(768 / 64, (BB * NN) / 64);
        qkv_gemm_kernel<<<grid, 256>>>(X, Wqkv);
    }

    {
        const int smem_bytes = (8*16*KP_STRIDE * 2) * 4 + 32*33*4;
        cudaFuncSetAttribute(attn_mma_kernel,
                             cudaFuncAttributeMaxDynamicSharedMemorySize,
                             smem_bytes);
        attn_mma_kernel<<<BB * 32, 256, smem_bytes>>>(rp, rel_len, btab);
    }

    {
        dim3 grid(256 / 64, (BB * NN) / 64);
        proj_gemm_kernel<<<grid, 256>>>(Wproj, bproj, out);
    }
}

// round 4
// speedup vs baseline: 3.3371x; 1.6947x over previous
#include <cuda_runtime.h>
#include <cuda_fp16.h>
#include <cstdint>

#define BB 8
#define NN 1024
#define CC 256
#define HH 8
#define HD 32
#define TABLE 10

// Scratch (allocation-free rule: __device__ globals)
__device__ __half g_ah [BB*NN*CC];      // X in fp16, row-major [8192][256]
__device__ __half g_wqt[3*CC*CC];       // W_qkv^T fp16 [768][256]
__device__ __half g_wpt[CC*CC];         // W_proj^T fp16 [256][256]
__device__ __half g_qh [BB*HH*NN*HD];   // pre-scaled q, fp16
__device__ __half g_kh [BB*HH*NN*HD];
__device__ __half g_vh [BB*HH*NN*HD];
__device__ __half g_xh [BB*NN*CC];      // attention output fp16 [8192][256]

// ---------------------------------------------------------------------------
// helpers
// ---------------------------------------------------------------------------
__device__ __forceinline__ void mma_f16(float* c, const uint32_t* a, const uint32_t* b) {
    asm volatile(
        "mma.sync.aligned.m16n8k16.row.col.f32.f16.f16.f32 "
        "{%0,%1,%2,%3},{%4,%5,%6,%7},{%8,%9},{%0,%1,%2,%3};\n"
        : "+f"(c[0]), "+f"(c[1]), "+f"(c[2]), "+f"(c[3])
        : "r"(a[0]), "r"(a[1]), "r"(a[2]), "r"(a[3]), "r"(b[0]), "r"(b[1]));
}
__device__ __forceinline__ void ldsm4(uint32_t* r, uint32_t addr) {
    asm volatile("ldmatrix.sync.aligned.m8n8.x4.shared.b16 {%0,%1,%2,%3},[%4];"
                 : "=r"(r[0]), "=r"(r[1]), "=r"(r[2]), "=r"(r[3]) : "r"(addr));
}
__device__ __forceinline__ uint32_t smem_u32(const void* p) {
    uint32_t a;
    asm("{ .reg .u64 t; cvta.to.shared.u64 t, %1; cvt.u32.u64 %0, t; }" : "=r"(a) : "l"(p));
    return a;
}
__device__ __forceinline__ void cp16(uint32_t dst, const void* src) {
    asm volatile("cp.async.ca.shared.global [%0],[%1],16;" :: "r"(dst), "l"(src));
}
__device__ __forceinline__ void cp_commit() { asm volatile("cp.async.commit_group;"); }
__device__ __forceinline__ void cp_wait0()  { asm volatile("cp.async.wait_group 0;"); }
__device__ __forceinline__ uint32_t h2pack(float lo, float hi) {
    __half2 h = __floats2half2_rn(lo, hi);
    return *(uint32_t*)&h;
}
__device__ __forceinline__ uint32_t prmt(uint32_t a, uint32_t b, uint32_t s) {
    uint32_t d;
    asm("prmt.b32 %0,%1,%2,%3;" : "=r"(d) : "r"(a), "r"(b), "r"(s));
    return d;
}

// ---------------------------------------------------------------------------
// Conversions
// ---------------------------------------------------------------------------
__global__ void __launch_bounds__(256) convert_x_kernel(const float4* __restrict__ X,
                                                        uint4* __restrict__ out)
{
    int idx = blockIdx.x * 256 + threadIdx.x;   // 8 floats each
    float4 a = X[idx * 2], b = X[idx * 2 + 1];
    __half2 h0 = __floats2half2_rn(a.x, a.y);
    __half2 h1 = __floats2half2_rn(a.z, a.w);
    __half2 h2 = __floats2half2_rn(b.x, b.y);
    __half2 h3 = __floats2half2_rn(b.z, b.w);
    out[idx] = make_uint4(*(uint32_t*)&h0, *(uint32_t*)&h1,
                          *(uint32_t*)&h2, *(uint32_t*)&h3);
}

// W [256][N] fp32 -> Wt [N][256] fp16
__global__ void __launch_bounds__(256) transpose_w_kernel(const float* __restrict__ W,
                                                          __half* __restrict__ Wt, int N)
{
    __shared__ float tile[32][33];
    int n0 = blockIdx.x * 32, k0 = blockIdx.y * 32;
    int tx = threadIdx.x & 31, ty = threadIdx.x >> 5;
    #pragma unroll
    for (int i = 0; i < 4; i++)
        tile[ty + i * 8][tx] = W[(k0 + ty + i * 8) * N + n0 + tx];
    __syncthreads();
    #pragma unroll
    for (int i = 0; i < 4; i++)
        Wt[(n0 + ty + i * 8) * 256 + k0 + tx] = __float2half_rn(tile[tx][ty + i * 8]);
}

// ---------------------------------------------------------------------------
// fp16 tensor-core GEMM: C[M,N] = A[M,256] @ Wt[N,256]^T
// block 128x128, K-chunks of 64, cp.async double buffer.
// PROJ=false: scatter to g_qh(scaled)/g_kh/g_vh.  PROJ=true: out = C + bias (fp32)
// ---------------------------------------------------------------------------
#define GS_ROW 9     // uint4 per smem row (8 data + 1 pad): LDSM conflict-free
#define GS_TILE (128 * GS_ROW)   // 1152 uint4 per tile
#define GS_BUF  (2 * GS_TILE)    // A + B per buffer

template<bool PROJ>
__global__ void __launch_bounds__(256) gemm_f16_kernel(
    const uint4* __restrict__ A4, const uint4* __restrict__ B4,
    float* __restrict__ outp, const float* __restrict__ bias)
{
    extern __shared__ uint4 smem4[];
    const int tid  = threadIdx.x;
    const int warp = tid >> 5, lane = tid & 31;
    const int g = lane >> 2, t = lane & 3;
    const int m0 = blockIdx.y * 128, n0 = blockIdx.x * 128;
    const int wm = warp >> 2, wn = warp & 3;    // 2x4 warps: 64 rows x 32 cols
    const uint32_t sb = smem_u32(smem4);
    const int arow = lane & 15, chi = lane >> 4;

    float acc[4][4][4];
    #pragma unroll
    for (int mt = 0; mt < 4; mt++)
        #pragma unroll
        for (int nt = 0; nt < 4; nt++)
            #pragma unroll
            for (int r = 0; r < 4; r++) acc[mt][nt][r] = 0.f;

    // async-load chunk c into buffer buf
    auto load_chunk = [&](int c, int buf) {
        #pragma unroll
        for (int i = 0; i < 4; i++) {
            int idx = i * 256 + tid;           // 1024 uint4 per tile
            int row = idx >> 3, cc = idx & 7;
            uint32_t da = sb + (uint32_t)(buf * GS_BUF + row * GS_ROW + cc) * 16;
            cp16(da, &A4[(long)(m0 + row) * 32 + c * 8 + cc]);
            uint32_t db = sb + (uint32_t)(buf * GS_BUF + GS_TILE + row * GS_ROW + cc) * 16;
            cp16(db, &B4[(long)(n0 + row) * 32 + c * 8 + cc]);
        }
        cp_commit();
    };

    load_chunk(0, 0);

    for (int c = 0; c < 4; c++) {
        cp_wait0();
        __syncthreads();
        if (c < 3) load_chunk(c + 1, (c + 1) & 1);
        const int bo = (c & 1) * GS_BUF;

        #pragma unroll
        for (int ks = 0; ks < 4; ks++) {
            uint32_t af[4][4];
            #pragma unroll
            for (int mt = 0; mt < 4; mt++)
                ldsm4(af[mt], sb + (uint32_t)(bo + (wm * 64 + mt * 16 + arow) * GS_ROW
                                              + ks * 2 + chi) * 16);
            uint32_t bf[2][4];
            #pragma unroll
            for (int np = 0; np < 2; np++)
                ldsm4(bf[np], sb + (uint32_t)(bo + GS_TILE
                                              + (wn * 32 + np * 16 + arow) * GS_ROW
                                              + ks * 2 + chi) * 16);
            #pragma unroll
            for (int mt = 0; mt < 4; mt++)
                #pragma unroll
                for (int nt = 0; nt < 4; nt++) {
                    uint32_t bb[2] = { bf[nt >> 1][nt & 1], bf[nt >> 1][(nt & 1) + 2] };
                    mma_f16(acc[mt][nt], af[mt], bb);
                }
        }
        __syncthreads();
    }

    if (PROJ) {
        #pragma unroll
        for (int mt = 0; mt < 4; mt++) {
            int m = m0 + wm * 64 + mt * 16 + g;
            #pragma unroll
            for (int nt = 0; nt < 4; nt++) {
                int col = n0 + wn * 32 + nt * 8 + 2 * t;
                float b0 = bias[col], b1 = bias[col + 1];
                *(float2*)&outp[(long)m * 256 + col] =
                    make_float2(acc[mt][nt][0] + b0, acc[mt][nt][1] + b1);
                *(float2*)&outp[(long)(m + 8) * 256 + col] =
                    make_float2(acc[mt][nt][2] + b0, acc[mt][nt][3] + b1);
            }
        }
    } else {
        const float scale = 0.17677669529663687f;   // 32^-0.5 folded into q
        #pragma unroll
        for (int mt = 0; mt < 4; mt++) {
            int m = m0 + wm * 64 + mt * 16 + g;
            int bb = m >> 10, nn = m & 1023;
            #pragma unroll
            for (int nt = 0; nt < 4; nt++) {
                int col = n0 + wn * 32 + nt * 8 + 2 * t;
                int sel = col >> 8, hh = (col >> 5) & 7, dd = col & 31;
                float c0 = acc[mt][nt][0], c1 = acc[mt][nt][1];
                float c2 = acc[mt][nt][2], c3 = acc[mt][nt][3];
                if (sel == 0) { c0 *= scale; c1 *= scale; c2 *= scale; c3 *= scale; }
                __half* dst = (sel == 0) ? g_qh : (sel == 1) ? g_kh : g_vh;
                long base = (((long)bb * HH + hh) * NN + nn) * HD + dd;
                *(__half2*)&dst[base]           = __floats2half2_rn(c0, c1);
                *(__half2*)&dst[base + 8 * HD]  = __floats2half2_rn(c2, c3);
            }
        }
    }
}

// ---------------------------------------------------------------------------
// Fused flash attention, fp16 mma.m16n8k16 (unchanged core from R3),
// epilogue now writes fp16 g_xh.
// ---------------------------------------------------------------------------
#define KP_STRIDE 40

__global__ void __launch_bounds__(256, 2) attn_mma_kernel(
    const int* __restrict__ rp, const int* __restrict__ rel_len,
    const float* __restrict__ bias_table)
{
    extern __shared__ uint32_t sm[];
    uint32_t* kp_s = sm;
    uint32_t* vp_s = kp_s + 8 * 16 * KP_STRIDE;
    int*      rp_s = (int*)(vp_s + 8 * 16 * KP_STRIDE);

    const int tid  = threadIdx.x;
    const int h    = tid >> 5;
    const int lane = tid & 31;
    const int g    = lane >> 2;
    const int t    = lane & 3;
    const int b    = blockIdx.x >> 5;
    const int row0 = (blockIdx.x & 31) * 32;

    const int mask_len = (int)(__int2float_rn(rel_len[b]) * 0.5f);
    float bt2 = 0.f;
    if (lane < TABLE)
        bt2 = bias_table[lane * HH + h] + ((lane > mask_len) ? -100.f : 0.f);

    uint32_t qa[2][2][4];
    {
        const uint32_t* qw = (const uint32_t*)g_qh;
        long rbase = ((long)(b * HH) + h) * NN + row0;
        #pragma unroll
        for (int mt = 0; mt < 2; mt++) {
            long rA = (rbase + mt * 16 + g) * 16;
            long rB = rA + 8 * 16;
            #pragma unroll
            for (int ks = 0; ks < 2; ks++) {
                int w = ks * 8 + t;
                qa[mt][ks][0] = qw[rA + w];
                qa[mt][ks][1] = qw[rB + w];
                qa[mt][ks][2] = qw[rA + w + 4];
                qa[mt][ks][3] = qw[rB + w + 4];
            }
        }
    }

    float o[2][4][4];
    #pragma unroll
    for (int mt = 0; mt < 2; mt++)
        #pragma unroll
        for (int nt = 0; nt < 4; nt++)
            #pragma unroll
            for (int r = 0; r < 4; r++) o[mt][nt][r] = 0.f;
    float mrow[2][2] = {{-1e30f, -1e30f}, {-1e30f, -1e30f}};
    float lrow[2][2] = {{0.f, 0.f}, {0.f, 0.f}};

    const uint32_t* kh = &kp_s[h * 16 * KP_STRIDE];
    const uint32_t* vh = &vp_s[h * 16 * KP_STRIDE];
    const __half* gk = g_kh;
    const __half* gv = g_vh;

    for (int j0 = 0; j0 < NN; j0 += 32) {
        __syncthreads();
        #pragma unroll
        for (int it = 0; it < 4; it++) {
            int idx = it * 256 + tid;
            int key = idx & 31;
            int q4  = (idx >> 5) & 3;
            int h2  = idx >> 7;
            long base = (((long)(b * HH + h2)) * NN + j0 + key) * 32;
            uint4 kw = *(const uint4*)(gk + base + q4 * 8);
            uint32_t* col = &kp_s[h2 * (16 * KP_STRIDE) + (q4 * 4) * KP_STRIDE + key];
            col[0 * KP_STRIDE] = kw.x;
            col[1 * KP_STRIDE] = kw.y;
            col[2 * KP_STRIDE] = kw.z;
            col[3 * KP_STRIDE] = kw.w;
        }
        #pragma unroll
        for (int it = 0; it < 2; it++) {
            int idx = it * 256 + tid;
            int d4   = idx & 3;
            int key2 = (idx >> 2) & 15;
            int h2   = idx >> 6;
            long base = (((long)(b * HH + h2)) * NN + j0 + 2 * key2) * 32;
            uint4 v0 = *(const uint4*)(gv + base + d4 * 8);
            uint4 v1 = *(const uint4*)(gv + base + 32 + d4 * 8);
            uint32_t* dst = &vp_s[h2 * (16 * KP_STRIDE) + key2 * KP_STRIDE + d4 * 8];
            *(uint4*)dst = make_uint4(
                prmt(v0.x, v1.x, 0x5410), prmt(v0.x, v1.x, 0x7632),
                prmt(v0.y, v1.y, 0x5410), prmt(v0.y, v1.y, 0x7632));
            *(uint4*)(dst + 4) = make_uint4(
                prmt(v0.z, v1.z, 0x5410), prmt(v0.z, v1.z, 0x7632),
                prmt(v0.w, v1.w, 0x5410), prmt(v0.w, v1.w, 0x7632));
        }
        {
            int rr = tid >> 3, cc = (tid & 7) * 4;
            int4 rv = *(const int4*)&rp[((long)b * NN + row0 + rr) * NN + j0 + cc];
            rp_s[rr * 33 + cc + 0] = rv.x;
            rp_s[rr * 33 + cc + 1] = rv.y;
            rp_s[rr * 33 + cc + 2] = rv.z;
            rp_s[rr * 33 + cc + 3] = rv.w;
        }
        __syncthreads();

        float c[2][4][4];
        #pragma unroll
        for (int mt = 0; mt < 2; mt++)
            #pragma unroll
            for (int nt = 0; nt < 4; nt++)
                #pragma unroll
                for (int r = 0; r < 4; r++) c[mt][nt][r] = 0.f;

        #pragma unroll
        for (int nt = 0; nt < 4; nt++)
            #pragma unroll
            for (int ks = 0; ks < 2; ks++) {
                uint32_t bf[2];
                bf[0] = kh[(ks * 8 + t) * KP_STRIDE + nt * 8 + g];
                bf[1] = kh[(ks * 8 + t + 4) * KP_STRIDE + nt * 8 + g];
                mma_f16(c[0][nt], qa[0][ks], bf);
                mma_f16(c[1][nt], qa[1][ks], bf);
            }

        #pragma unroll
        for (int mt = 0; mt < 2; mt++) {
            int rA = mt * 16 + g;
            int rB = rA + 8;
            float mx0 = -1e30f, mx1 = -1e30f;
            #pragma unroll
            for (int nt = 0; nt < 4; nt++) {
                int colb = nt * 8 + 2 * t;
                int r00 = rp_s[rA * 33 + colb], r01 = rp_s[rA * 33 + colb + 1];
                int r10 = rp_s[rB * 33 + colb], r11 = rp_s[rB * 33 + colb + 1];
                c[mt][nt][0] += __shfl_sync(0xffffffffu, bt2, r00);
                c[mt][nt][1] += __shfl_sync(0xffffffffu, bt2, r01);
                c[mt][nt][2] += __shfl_sync(0xffffffffu, bt2, r10);
                c[mt][nt][3] += __shfl_sync(0xffffffffu, bt2, r11);
                mx0 = fmaxf(mx0, fmaxf(c[mt][nt][0], c[mt][nt][1]));
                mx1 = fmaxf(mx1, fmaxf(c[mt][nt][2], c[mt][nt][3]));
            }
            mx0 = fmaxf(mx0, __shfl_xor_sync(0xffffffffu, mx0, 1));
            mx0 = fmaxf(mx0, __shfl_xor_sync(0xffffffffu, mx0, 2));
            mx1 = fmaxf(mx1, __shfl_xor_sync(0xffffffffu, mx1, 1));
            mx1 = fmaxf(mx1, __shfl_xor_sync(0xffffffffu, mx1, 2));

            float nm0 = fmaxf(mrow[mt][0], mx0);
            float nm1 = fmaxf(mrow[mt][1], mx1);
            float corr0 = __expf(mrow[mt][0] - nm0);
            float corr1 = __expf(mrow[mt][1] - nm1);
            float rs0 = 0.f, rs1 = 0.f;
            #pragma unroll
            for (int nt = 0; nt < 4; nt++) {
                c[mt][nt][0] = __expf(c[mt][nt][0] - nm0);
                c[mt][nt][1] = __expf(c[mt][nt][1] - nm0);
                c[mt][nt][2] = __expf(c[mt][nt][2] - nm1);
                c[mt][nt][3] = __expf(c[mt][nt][3] - nm1);
                rs0 += c[mt][nt][0] + c[mt][nt][1];
                rs1 += c[mt][nt][2] + c[mt][nt][3];
            }
            rs0 += __shfl_xor_sync(0xffffffffu, rs0, 1);
            rs0 += __shfl_xor_sync(0xffffffffu, rs0, 2);
            rs1 += __shfl_xor_sync(0xffffffffu, rs1, 1);
            rs1 += __shfl_xor_sync(0xffffffffu, rs1, 2);
            lrow[mt][0] = lrow[mt][0] * corr0 + rs0;
            lrow[mt][1] = lrow[mt][1] * corr1 + rs1;
            #pragma unroll
            for (int nt = 0; nt < 4; nt++) {
                o[mt][nt][0] *= corr0; o[mt][nt][1] *= corr0;
                o[mt][nt][2] *= corr1; o[mt][nt][3] *= corr1;
            }
            mrow[mt][0] = nm0;
            mrow[mt][1] = nm1;
        }

        uint32_t pa[2][2][4];
        #pragma unroll
        for (int mt = 0; mt < 2; mt++)
            #pragma unroll
            for (int ks = 0; ks < 2; ks++) {
                pa[mt][ks][0] = h2pack(c[mt][2*ks  ][0], c[mt][2*ks  ][1]);
                pa[mt][ks][1] = h2pack(c[mt][2*ks  ][2], c[mt][2*ks  ][3]);
                pa[mt][ks][2] = h2pack(c[mt][2*ks+1][0], c[mt][2*ks+1][1]);
                pa[mt][ks][3] = h2pack(c[mt][2*ks+1][2], c[mt][2*ks+1][3]);
            }

        #pragma unroll
        for (int ks = 0; ks < 2; ks++)
            #pragma unroll
            for (int nt = 0; nt < 4; nt++) {
                uint32_t bf[2];
                bf[0] = vh[(ks * 8 + t) * KP_STRIDE + nt * 8 + g];
                bf[1] = vh[(ks * 8 + t + 4) * KP_STRIDE + nt * 8 + g];
                mma_f16(o[0][nt], pa[0][ks], bf);
                mma_f16(o[1][nt], pa[1][ks], bf);
            }
    }

    // epilogue: normalize, store fp16 to g_xh (A-matrix layout for proj GEMM)
    #pragma unroll
    for (int mt = 0; mt < 2; mt++) {
        float i0 = 1.f / lrow[mt][0];
        float i1 = 1.f / lrow[mt][1];
        int rA = row0 + mt * 16 + g;
        #pragma unroll
        for (int nt = 0; nt < 4; nt++) {
            int col = h * HD + nt * 8 + 2 * t;
            *(__half2*)&g_xh[((long)b * NN + rA) * CC + col] =
                __floats2half2_rn(o[mt][nt][0] * i0, o[mt][nt][1] * i0);
            *(__half2*)&g_xh[((long)b * NN + rA + 8) * CC + col] =
                __floats2half2_rn(o[mt][nt][2] * i1, o[mt][nt][3] * i1);
        }
    }
}

// ---------------------------------------------------------------------------
extern "C" void kernel_launch(void* const* d_in, const int* in_sizes, int n_in,
                              void* d_out, int out_size)
{
    const float* X       = (const float*)d_in[0];
    const int*   rp      = (const int*)  d_in[1];
    const int*   rel_len = (const int*)  d_in[2];
    const float* Wqkv    = (const float*)d_in[3];
    const float* Wproj   = (const float*)d_in[4];
    const float* bproj   = (const float*)d_in[5];
    const float* btab    = (const float*)d_in[6];
    float* out = (float*)d_out;

    __half* d_ah;   cudaGetSymbolAddress((void**)&d_ah,  g_ah);
    __half* d_wqt;  cudaGetSymbolAddress((void**)&d_wqt, g_wqt);
    __half* d_wpt;  cudaGetSymbolAddress((void**)&d_wpt, g_wpt);

    const int gemm_smem = 2 * GS_BUF * 16;   // 73728 B

    // converts
    convert_x_kernel<<<1024, 256>>>((const float4*)X, (uint4*)d_ah);
    transpose_w_kernel<<<dim3(24, 8), 256>>>(Wqkv,  d_wqt, 768);
    transpose_w_kernel<<<dim3(8, 8),  256>>>(Wproj, d_wpt, 256);

    // qkv GEMM (fp16 MMA)
    cudaFuncSetAttribute(gemm_f16_kernel<false>,
                         cudaFuncAttributeMaxDynamicSharedMemorySize, gemm_smem);
    gemm_f16_kernel<false><<<dim3(6, 64), 256, gemm_smem>>>(
        (const uint4*)d_ah, (const uint4*)d_wqt, nullptr, nullptr);

    // attention
    {
        const int smem_bytes = (8*16*KP_STRIDE * 2) * 4 + 32*33*4;
        cudaFuncSetAttribute(attn_mma_kernel,
                             cudaFuncAttributeMaxDynamicSharedMemorySize, smem_bytes);
        attn_mma_kernel<<<BB * 32, 256, smem_bytes>>>(rp, rel_len, btab);
    }

    // proj GEMM (fp16 MMA) + bias -> fp32 out
    cudaFuncSetAttribute(gemm_f16_kernel<true>,
                         cudaFuncAttributeMaxDynamicSharedMemorySize, gemm_smem);
    __half* d_xh;  cudaGetSymbolAddress((void**)&d_xh, g_xh);
    gemm_f16_kernel<true><<<dim3(2, 64), 256, gemm_smem>>>(
        (const uint4*)d_xh, (const uint4*)d_wpt, out, bproj);
}